// round 15
// baseline (speedup 1.0000x reference)
#include <cuda_runtime.h>
#include <cstdint>

#define Bb 64
#define Nn 196
#define Hh 512
#define Aa 512
#define Vv 20000
#define Ll 20
#define Tt 19

// ---------------- scratch ----------------------------------------------------
__device__ float g_enc_proj[Bb*Nn*Aa];        // 25.7 MB
__device__ float g_h[Bb*Hh];
__device__ float g_c[Bb*Hh];
__device__ float g_context[Bb*Hh];
__device__ float g_gates_x[Tt*Bb*4*Hh];
__device__ float g_dec_part[4*Bb*Aa];
__device__ float g_gates_part[8*Bb*4*Hh];     // split-K=8 partials (4 MB)
__device__ float g_hall[1280*Hh];

__device__ __forceinline__ float tanh_fast(float x) {
    float y; asm("tanh.approx.f32 %0, %1;" : "=f"(y) : "f"(x)); return y;
}
__device__ __forceinline__ float sigmoid_fast(float x) {
    return 1.0f / (1.0f + __expf(-x));
}
__device__ __forceinline__ unsigned cvt_tf32(float x) {
    unsigned r; asm("cvt.rna.tf32.f32 %0, %1;" : "=r"(r) : "f"(x)); return r;
}
__device__ __forceinline__ void mma_tf32(float c[4],
                                         unsigned a0, unsigned a1, unsigned a2, unsigned a3,
                                         unsigned b0, unsigned b1) {
    asm("mma.sync.aligned.m16n8k8.row.col.f32.tf32.tf32.f32 "
        "{%0,%1,%2,%3}, {%4,%5,%6,%7}, {%8,%9}, {%0,%1,%2,%3};"
        : "+f"(c[0]), "+f"(c[1]), "+f"(c[2]), "+f"(c[3])
        : "r"(a0), "r"(a1), "r"(a2), "r"(a3), "r"(b0), "r"(b1));
}

// ============ tensor-core tf32 NT GEMM: 128x256 tile, 64x64 warp tiles =======
// BK=16, 256 threads, 8 warps (2M x 4N). Fragment-major SMEM.
// sA[st][k8*1024 + row*8 + qc*2 + r]  (128 rows), sB[st][k8*2048 + row*8 + ...] (256 rows)
__global__ __launch_bounds__(256)
void gemm_tc(const float* __restrict__ A,
             const float* __restrict__ Bw, int ldb,
             const float* __restrict__ bias,
             const float* __restrict__ bias2,
             float* __restrict__ C,
             int Mvalid, int N, int K,
             const int* __restrict__ caps, int storemode)
{
    __shared__ unsigned sA[2][2048];   // 8 KB / stage
    __shared__ unsigned sB[2][4096];   // 16 KB / stage  (total 48 KB)

    const int tid  = threadIdx.x;
    const int m0   = blockIdx.y * 128;
    const int n0   = blockIdx.x * 256;
    const int lane = tid & 31;
    const int wid  = tid >> 5;
    const int wm   = (wid & 1) * 64;
    const int wn   = (wid >> 1) * 64;
    const int qr   = lane >> 2;
    const int qc   = lane & 3;

    // A loader: row = tid>>1 (0..127), k-seg = (tid&1)*8
    const int lrowA = tid >> 1;
    const int lkA   = (tid & 1) << 3;
    const int sbaseA = (lkA >> 3) * 1024 + lrowA * 8;

    const float* arow;
    {
        int am = m0 + lrowA;
        if (caps) {
            int mm = (am < Mvalid) ? am : 0;
            int ci = caps[(mm & 63) * Ll + (mm >> 6)];
            ci = ci < 0 ? 0 : (ci >= Vv ? Vv - 1 : ci);
            arow = A + (size_t)ci * K;
        } else {
            int mm = (am < Mvalid) ? am : (Mvalid - 1);
            arow = A + (size_t)mm * K;
        }
    }
    // B loader: row = tid (0..255), loads 16 floats
    const int bn = n0 + tid;
    const bool bval = (bn < N);
    const float* brow = Bw + (size_t)(bval ? bn : 0) * ldb;

    float acc[4][8][4];
#pragma unroll
    for (int i = 0; i < 4; i++)
#pragma unroll
        for (int j = 0; j < 8; j++)
#pragma unroll
            for (int q = 0; q < 4; q++) acc[i][j][q] = 0.0f;

    float4 av0, av1, bv0, bv1, bv2, bv3;
    auto fetch = [&](int k0) {
        av0 = *(const float4*)(arow + k0 + lkA);
        av1 = *(const float4*)(arow + k0 + lkA + 4);
        if (bval) {
            bv0 = *(const float4*)(brow + k0);
            bv1 = *(const float4*)(brow + k0 + 4);
            bv2 = *(const float4*)(brow + k0 + 8);
            bv3 = *(const float4*)(brow + k0 + 12);
        } else {
            bv0 = bv1 = bv2 = bv3 = make_float4(0.f, 0.f, 0.f, 0.f);
        }
    };
    auto store_stage = [&](int s) {
        uint4 p0, p1;
        // A: permuted pack {v0,v4,v1,v5},{v2,v6,v3,v7}
        p0.x = __float_as_uint(av0.x); p0.y = __float_as_uint(av1.x);
        p0.z = __float_as_uint(av0.y); p0.w = __float_as_uint(av1.y);
        p1.x = __float_as_uint(av0.z); p1.y = __float_as_uint(av1.z);
        p1.z = __float_as_uint(av0.w); p1.w = __float_as_uint(av1.w);
        *(uint4*)&sA[s][sbaseA]     = p0;
        *(uint4*)&sA[s][sbaseA + 4] = p1;
        // B k8=0 from bv0,bv1
        p0.x = __float_as_uint(bv0.x); p0.y = __float_as_uint(bv1.x);
        p0.z = __float_as_uint(bv0.y); p0.w = __float_as_uint(bv1.y);
        p1.x = __float_as_uint(bv0.z); p1.y = __float_as_uint(bv1.z);
        p1.z = __float_as_uint(bv0.w); p1.w = __float_as_uint(bv1.w);
        *(uint4*)&sB[s][tid * 8]     = p0;
        *(uint4*)&sB[s][tid * 8 + 4] = p1;
        // B k8=1 from bv2,bv3
        p0.x = __float_as_uint(bv2.x); p0.y = __float_as_uint(bv3.x);
        p0.z = __float_as_uint(bv2.y); p0.w = __float_as_uint(bv3.y);
        p1.x = __float_as_uint(bv2.z); p1.y = __float_as_uint(bv3.z);
        p1.z = __float_as_uint(bv2.w); p1.w = __float_as_uint(bv3.w);
        *(uint4*)&sB[s][2048 + tid * 8]     = p0;
        *(uint4*)&sB[s][2048 + tid * 8 + 4] = p1;
    };

    fetch(0);
    store_stage(0);
    __syncthreads();

    const int steps = K >> 4;
    for (int it = 0; it < steps; it++) {
        const int s = it & 1;
        if (it + 1 < steps) fetch((it + 1) << 4);

#pragma unroll
        for (int k8 = 0; k8 < 2; k8++) {
            const unsigned* baseA = &sA[s][k8 * 1024 + qc * 2];
            const unsigned* baseB = &sB[s][k8 * 2048 + qc * 2];
            uint2 afl[4], afh[4], bf[8];
#pragma unroll
            for (int mt = 0; mt < 4; mt++) {
                const int r = wm + mt * 16 + qr;
                afl[mt] = *(const uint2*)&baseA[r * 8];
                afh[mt] = *(const uint2*)&baseA[(r + 8) * 8];
            }
#pragma unroll
            for (int nt = 0; nt < 8; nt++) {
                const int n = wn + nt * 8 + qr;
                bf[nt] = *(const uint2*)&baseB[n * 8];
            }
#pragma unroll
            for (int mt = 0; mt < 4; mt++)
#pragma unroll
                for (int nt = 0; nt < 8; nt++)
                    mma_tf32(acc[mt][nt],
                             afl[mt].x, afh[mt].x, afl[mt].y, afh[mt].y,
                             bf[nt].x, bf[nt].y);
        }

        if (it + 1 < steps) store_stage(s ^ 1);
        __syncthreads();
    }

#pragma unroll
    for (int mt = 0; mt < 4; mt++) {
#pragma unroll
        for (int nt = 0; nt < 8; nt++) {
#pragma unroll
            for (int half = 0; half < 2; half++) {
                const int m = m0 + wm + mt * 16 + qr + half * 8;
                if (m >= Mvalid) continue;
                const int col = n0 + wn + nt * 8 + 2 * qc;
#pragma unroll
                for (int q = 0; q < 2; q++) {
                    const int n = col + q;
                    if (n >= N) continue;
                    float v = acc[mt][nt][half * 2 + q];
                    if (bias)  v += bias[n];
                    if (bias2) v += bias2[n];
                    if (storemode == 0) {
                        C[(size_t)m * N + n] = v;
                    } else {
                        const int t = m >> 6, b = m & 63;
                        C[((size_t)b * Ll + t + 1) * Vv + n] = v;
                    }
                }
            }
        }
    }
}

// ============ tensor-core gates GEMM (recurrent; RNA rounding) ===============
// grid (16, 8): n0 = bx*128, K chunk s = by (128 wide). Partials P[s][64][2048].
__global__ __launch_bounds__(256)
void gates_tc(const float* __restrict__ W_ih,
              const float* __restrict__ W_hh)
{
    __shared__ unsigned sA[2][1024];
    __shared__ unsigned sB[2][2048];

    const int tid  = threadIdx.x;
    const int n0   = blockIdx.x * 128;
    const int s    = blockIdx.y;
    const int kbeg = s * 128;
    const int lane = tid & 31;
    const int wid  = tid >> 5;
    const int wm   = (wid & 1) * 32;
    const int wn   = (wid >> 1) * 32;
    const int qr   = lane >> 2;
    const int qc   = lane & 3;

    const int lrow = tid >> 1;
    const int lk   = (tid & 1) << 3;
    const int k8i  = lk >> 3;
    const int sbB  = k8i * 1024 + lrow * 8;
    const int sbA  = k8i * 512  + lrow * 8;

    const float* abase = (s < 4) ? g_context : g_h;
    const int    akoff = (s < 4) ? kbeg : (kbeg - 512);
    const float* asrc  = abase + (size_t)lrow * 512 + akoff;

    const int brn = n0 + lrow;
    const float* bsrc = (s < 4) ? (W_ih + (size_t)brn * 1024 + 512 + kbeg)
                                : (W_hh + (size_t)brn * 512 + (kbeg - 512));

    float acc[2][4][4];
#pragma unroll
    for (int i = 0; i < 2; i++)
#pragma unroll
        for (int j = 0; j < 4; j++)
#pragma unroll
            for (int q = 0; q < 4; q++) acc[i][j][q] = 0.0f;

    float4 av0, av1, bv0, bv1;
    auto fetch = [&](int k0) {
        if (tid < 128) {
            av0 = *(const float4*)(asrc + k0 + lk);
            av1 = *(const float4*)(asrc + k0 + lk + 4);
        }
        bv0 = *(const float4*)(bsrc + k0 + lk);
        bv1 = *(const float4*)(bsrc + k0 + lk + 4);
    };
    auto store_stage = [&](int st) {
        uint4 p0, p1;
        if (tid < 128) {
            p0.x = cvt_tf32(av0.x); p0.y = cvt_tf32(av1.x);
            p0.z = cvt_tf32(av0.y); p0.w = cvt_tf32(av1.y);
            p1.x = cvt_tf32(av0.z); p1.y = cvt_tf32(av1.z);
            p1.z = cvt_tf32(av0.w); p1.w = cvt_tf32(av1.w);
            *(uint4*)&sA[st][sbA]     = p0;
            *(uint4*)&sA[st][sbA + 4] = p1;
        }
        p0.x = cvt_tf32(bv0.x); p0.y = cvt_tf32(bv1.x);
        p0.z = cvt_tf32(bv0.y); p0.w = cvt_tf32(bv1.y);
        p1.x = cvt_tf32(bv0.z); p1.y = cvt_tf32(bv1.z);
        p1.z = cvt_tf32(bv0.w); p1.w = cvt_tf32(bv1.w);
        *(uint4*)&sB[st][sbB]     = p0;
        *(uint4*)&sB[st][sbB + 4] = p1;
    };

    fetch(0);
    store_stage(0);
    __syncthreads();

    for (int it = 0; it < 8; it++) {
        const int st = it & 1;
        if (it + 1 < 8) fetch((it + 1) << 4);

#pragma unroll
        for (int k8 = 0; k8 < 2; k8++) {
            const unsigned* baseA = &sA[st][k8 * 512 + qc * 2];
            const unsigned* baseB = &sB[st][k8 * 1024 + qc * 2];
            uint2 afl[2], afh[2], bf[4];
#pragma unroll
            for (int mt = 0; mt < 2; mt++) {
                const int r = wm + mt * 16 + qr;
                afl[mt] = *(const uint2*)&baseA[r * 8];
                afh[mt] = *(const uint2*)&baseA[(r + 8) * 8];
            }
#pragma unroll
            for (int nt = 0; nt < 4; nt++) {
                const int n = wn + nt * 8 + qr;
                bf[nt] = *(const uint2*)&baseB[n * 8];
            }
#pragma unroll
            for (int mt = 0; mt < 2; mt++)
#pragma unroll
                for (int nt = 0; nt < 4; nt++)
                    mma_tf32(acc[mt][nt],
                             afl[mt].x, afh[mt].x, afl[mt].y, afh[mt].y,
                             bf[nt].x, bf[nt].y);
        }

        if (it + 1 < 8) store_stage(st ^ 1);
        __syncthreads();
    }

    float* P = g_gates_part + (size_t)s * 64 * 2048;
#pragma unroll
    for (int mt = 0; mt < 2; mt++) {
#pragma unroll
        for (int nt = 0; nt < 4; nt++) {
#pragma unroll
            for (int half = 0; half < 2; half++) {
                const int m = wm + mt * 16 + qr + half * 8;
                const int n = n0 + wn + nt * 8 + 2 * qc;
                float2 v2 = make_float2(acc[mt][nt][half * 2], acc[mt][nt][half * 2 + 1]);
                *(float2*)&P[(size_t)m * 2048 + n] = v2;
            }
        }
    }
}

// ============ small-M (64) split-K GEMM (dec; fp32) ==========================
__global__ void gemm64_split(const float* __restrict__ A1,
                             const float* __restrict__ W1,
                             float* __restrict__ P)
{
    __shared__ float As[16][64];
    __shared__ float Ws[16][64];
    const int tid = threadIdx.x;
    const int n0 = blockIdx.x * 64;
    const int s  = blockIdx.y;
    const int kbeg = s * 128, kend = kbeg + 128;

    const int row = tid >> 2;
    const int kc  = (tid & 3) << 2;
    const int tx = tid & 15, ty = tid >> 4;

    float acc[4][4];
#pragma unroll
    for (int i = 0; i < 4; i++)
#pragma unroll
        for (int j = 0; j < 4; j++) acc[i][j] = 0.0f;

    for (int k0 = kbeg; k0 < kend; k0 += 16) {
        float4 av = *(const float4*)(A1 + (size_t)row * 512 + k0 + kc);
        float4 wv = *(const float4*)(W1 + (size_t)(n0 + row) * 512 + k0 + kc);
        As[kc+0][row] = av.x; As[kc+1][row] = av.y; As[kc+2][row] = av.z; As[kc+3][row] = av.w;
        Ws[kc+0][row] = wv.x; Ws[kc+1][row] = wv.y; Ws[kc+2][row] = wv.z; Ws[kc+3][row] = wv.w;
        __syncthreads();
#pragma unroll
        for (int kk = 0; kk < 16; kk++) {
            float4 a4 = *(const float4*)&As[kk][ty << 2];
            float4 w4 = *(const float4*)&Ws[kk][tx << 2];
            float a_[4] = {a4.x, a4.y, a4.z, a4.w};
            float w_[4] = {w4.x, w4.y, w4.z, w4.w};
#pragma unroll
            for (int i = 0; i < 4; i++)
#pragma unroll
                for (int j = 0; j < 4; j++) acc[i][j] += a_[i] * w_[j];
        }
        __syncthreads();
    }

#pragma unroll
    for (int i = 0; i < 4; i++) {
        const int m = (ty << 2) + i;
        float4 o = make_float4(acc[i][0], acc[i][1], acc[i][2], acc[i][3]);
        *(float4*)(P + ((size_t)(s * 64 + m) * 512 + n0 + (tx << 2))) = o;
    }
}

// ============ fused attention ===============================================
__global__ void attn_step(const float* __restrict__ enc_out,
                          const float* __restrict__ dec_bv,
                          const float* __restrict__ eW,
                          const float* __restrict__ eb)
{
    __shared__ float dec_s[Aa];
    __shared__ float eW_s[Aa];
    __shared__ float sc[224];
    __shared__ float red[512];

    const int b = blockIdx.x, tid = threadIdx.x;

    {
        float v = dec_bv[tid];
#pragma unroll
        for (int s = 0; s < 4; s++) v += g_dec_part[(size_t)(s * 64 + b) * Aa + tid];
        dec_s[tid] = v;
        eW_s[tid] = eW[tid];
    }
    const float eb0 = eb[0];
    __syncthreads();

    const int wid = tid >> 5, lane = tid & 31;
    for (int n = wid; n < Nn; n += 16) {
        const float* ep = g_enc_proj + ((size_t)b * Nn + n) * Aa;
        float acc = 0.0f;
#pragma unroll 4
        for (int a = lane; a < Aa; a += 32)
            acc += tanh_fast(ep[a] + dec_s[a]) * eW_s[a];
#pragma unroll
        for (int o = 16; o; o >>= 1) acc += __shfl_xor_sync(0xffffffffu, acc, o);
        if (lane == 0) sc[n] = acc + eb0;
    }
    __syncthreads();

    float v = (tid < Nn) ? sc[tid] : -1e30f;
    red[tid] = v; __syncthreads();
    for (int s = 256; s; s >>= 1) { if (tid < s) red[tid] = fmaxf(red[tid], red[tid+s]); __syncthreads(); }
    const float mx = red[0]; __syncthreads();
    float e = (tid < Nn) ? __expf(v - mx) : 0.0f;
    red[tid] = e; __syncthreads();
    for (int s = 256; s; s >>= 1) { if (tid < s) red[tid] += red[tid+s]; __syncthreads(); }
    const float inv = 1.0f / red[0];
    if (tid < Nn) sc[tid] = e * inv;
    __syncthreads();

    const float* eo = enc_out + (size_t)b * Nn * Hh + tid;
    float acc = 0.0f;
#pragma unroll 4
    for (int n = 0; n < Nn; n++) acc += sc[n] * eo[(size_t)n * Hh];
    g_context[b * Hh + tid] = acc;
}

// ============ LSTM cell: fold 8 gate partials + nonlinearity =================
__global__ void cell_update(int t)
{
    const int b = blockIdx.x, u = threadIdx.x;
    const float* gx = g_gates_x + ((size_t)t * Bb + b) * 4 * Hh;
    float g[4];
#pragma unroll
    for (int gi = 0; gi < 4; gi++) {
        const int col = gi * Hh + u;
        float v = gx[col];
#pragma unroll
        for (int s = 0; s < 8; s++) v += g_gates_part[(size_t)(s * 64 + b) * (4*Hh) + col];
        g[gi] = v;
    }
    const int idx = b * Hh + u;
    const float cn = sigmoid_fast(g[1]) * g_c[idx] + sigmoid_fast(g[0]) * tanh_fast(g[2]);
    const float hn = sigmoid_fast(g[3]) * tanh_fast(cn);
    g_c[idx] = cn;
    g_h[idx] = hn;
    g_hall[(size_t)(t * Bb + b) * Hh + u] = hn;
}

// ============ init + zero (fused) ============================================
__global__ void init_all(float* __restrict__ out)
{
    const int gi = blockIdx.x * blockDim.x + threadIdx.x;
    if (gi < Bb * Hh) { g_h[gi] = 0.0f; g_c[gi] = 0.0f; }
    for (int i = gi; i < Bb * Vv; i += gridDim.x * blockDim.x) {
        const int b = i / Vv, v = i - b * Vv;
        out[(size_t)b * Ll * Vv + v] = 0.0f;
    }
}

// ============ launch =========================================================
extern "C" void kernel_launch(void* const* d_in, const int* in_sizes, int n_in,
                              void* d_out, int out_size)
{
    const float* enc_out  = (const float*)d_in[0];
    const int*   captions = (const int*)d_in[1];
    const float* emb      = (const float*)d_in[2];
    const float* W_ih     = (const float*)d_in[3];
    const float* W_hh     = (const float*)d_in[4];
    const float* b_ih     = (const float*)d_in[5];
    const float* b_hh     = (const float*)d_in[6];
    const float* enc_W    = (const float*)d_in[7];
    const float* enc_b    = (const float*)d_in[8];
    const float* dec_W    = (const float*)d_in[9];
    const float* dec_b    = (const float*)d_in[10];
    const float* energy_W = (const float*)d_in[11];
    const float* energy_b = (const float*)d_in[12];
    const float* fc_W     = (const float*)d_in[13];
    const float* fc_b     = (const float*)d_in[14];
    float* out = (float*)d_out;

    float *p_enc_proj, *p_gates_x, *p_hall, *p_h, *p_dec_part;
    cudaGetSymbolAddress((void**)&p_enc_proj, g_enc_proj);
    cudaGetSymbolAddress((void**)&p_gates_x,  g_gates_x);
    cudaGetSymbolAddress((void**)&p_hall,     g_hall);
    cudaGetSymbolAddress((void**)&p_h,        g_h);
    cudaGetSymbolAddress((void**)&p_dec_part, g_dec_part);

    init_all<<<256, 256>>>(out);

    // enc_proj : [12544, 512] K=512 ; N=512 -> 2 n-tiles of 256
    gemm_tc<<<dim3(512/256, 12544/128), 256>>>(enc_out, enc_W, 512, enc_b, nullptr,
                                               p_enc_proj, 12544, 512, 512, nullptr, 0);
    // gates_x : [1216, 2048] K=512 (embedding gather) ; 8 n-tiles
    gemm_tc<<<dim3(2048/256, 10), 256>>>(emb, W_ih, 1024, b_ih, b_hh,
                                         p_gates_x, 1216, 2048, 512, captions, 0);

    for (int t = 0; t < Tt; t++) {
        // dec partials (fp32 SIMT, split-K=4)
        gemm64_split<<<dim3(Aa/64, 4), 256>>>(p_h, dec_W, p_dec_part);
        // dec-fold + scores + softmax + context
        attn_step<<<Bb, 512>>>(enc_out, dec_b, energy_W, energy_b);
        // gates partials via tensor cores, split-K=8 (RNA)
        gates_tc<<<dim3(16, 8), 256>>>(W_ih, W_hh);
        // cell (folds 8 partials)
        cell_update<<<Bb, Hh>>>(t);
    }

    // fc : [1216, 20000] K=512 ; 79 n-tiles of 256
    gemm_tc<<<dim3((Vv + 255)/256, 10), 256>>>(p_hall, fc_W, 512, fc_b, nullptr,
                                               out, 1216, Vv, 512, nullptr, 1);
}

// round 16
// speedup vs baseline: 1.0706x; 1.0706x over previous
#include <cuda_runtime.h>
#include <cstdint>

#define Bb 64
#define Nn 196
#define Hh 512
#define Aa 512
#define Vv 20000
#define Ll 20
#define Tt 19

// ---------------- scratch ----------------------------------------------------
__device__ float g_enc_proj[Bb*Nn*Aa];        // 25.7 MB
__device__ float g_h[Bb*Hh];
__device__ float g_c[Bb*Hh];
__device__ float g_context[Bb*Hh];
__device__ float g_gates_x[Tt*Bb*4*Hh];
__device__ float g_dec_part[4*Bb*Aa];
__device__ float g_gates_part[8*Bb*4*Hh];     // split-K=8 partials (4 MB)
__device__ float g_hall[1280*Hh];

__device__ __forceinline__ float tanh_fast(float x) {
    float y; asm("tanh.approx.f32 %0, %1;" : "=f"(y) : "f"(x)); return y;
}
__device__ __forceinline__ float sigmoid_fast(float x) {
    return 1.0f / (1.0f + __expf(-x));
}
// HMMA tf32 ignores the low 13 mantissa bits of the 32-bit operand register,
// so raw fp32 acts as truncation-rounded tf32 (R10 numerics; rel_err 5.6e-4).
__device__ __forceinline__ void mma_tf32(float c[4],
                                         unsigned a0, unsigned a1, unsigned a2, unsigned a3,
                                         unsigned b0, unsigned b1) {
    asm("mma.sync.aligned.m16n8k8.row.col.f32.tf32.tf32.f32 "
        "{%0,%1,%2,%3}, {%4,%5,%6,%7}, {%8,%9}, {%0,%1,%2,%3};"
        : "+f"(c[0]), "+f"(c[1]), "+f"(c[2]), "+f"(c[3])
        : "r"(a0), "r"(a1), "r"(a2), "r"(a3), "r"(b0), "r"(b1));
}

// ============ tensor-core tf32 NT GEMM (proven R10: 128x128, 64x32 warps) ====
__global__ __launch_bounds__(256, 2)
void gemm_tc(const float* __restrict__ A,
             const float* __restrict__ Bw, int ldb,
             const float* __restrict__ bias,
             const float* __restrict__ bias2,
             float* __restrict__ C,
             int Mvalid, int N, int K,
             const int* __restrict__ caps, int storemode)
{
    __shared__ unsigned sA[2][2048];
    __shared__ unsigned sB[2][2048];

    const int tid  = threadIdx.x;
    const int m0   = blockIdx.y * 128;
    const int n0   = blockIdx.x * 128;
    const int lane = tid & 31;
    const int wid  = tid >> 5;
    const int wm   = (wid & 1) * 64;
    const int wn   = (wid >> 1) * 32;
    const int qr   = lane >> 2;
    const int qc   = lane & 3;

    const int lrow = tid >> 1;
    const int lk   = (tid & 1) << 3;
    const int sbase = (lk >> 3) * 1024 + lrow * 8;

    const float* arow;
    {
        int am = m0 + lrow;
        if (caps) {
            int mm = (am < Mvalid) ? am : 0;
            int ci = caps[(mm & 63) * Ll + (mm >> 6)];
            ci = ci < 0 ? 0 : (ci >= Vv ? Vv - 1 : ci);
            arow = A + (size_t)ci * K;
        } else {
            int mm = (am < Mvalid) ? am : (Mvalid - 1);
            arow = A + (size_t)mm * K;
        }
    }
    const int bn = n0 + lrow;
    const bool bval = (bn < N);
    const float* brow = Bw + (size_t)(bval ? bn : 0) * ldb;

    float acc[4][4][4];
#pragma unroll
    for (int i = 0; i < 4; i++)
#pragma unroll
        for (int j = 0; j < 4; j++)
#pragma unroll
            for (int q = 0; q < 4; q++) acc[i][j][q] = 0.0f;

    float4 av0, av1, bv0, bv1;
    auto fetch = [&](int k0) {
        av0 = *(const float4*)(arow + k0 + lk);
        av1 = *(const float4*)(arow + k0 + lk + 4);
        bv0 = bval ? *(const float4*)(brow + k0 + lk)     : make_float4(0.f,0.f,0.f,0.f);
        bv1 = bval ? *(const float4*)(brow + k0 + lk + 4) : make_float4(0.f,0.f,0.f,0.f);
    };
    auto store_stage = [&](int s) {
        uint4 p0, p1;
        p0.x = __float_as_uint(av0.x); p0.y = __float_as_uint(av1.x);
        p0.z = __float_as_uint(av0.y); p0.w = __float_as_uint(av1.y);
        p1.x = __float_as_uint(av0.z); p1.y = __float_as_uint(av1.z);
        p1.z = __float_as_uint(av0.w); p1.w = __float_as_uint(av1.w);
        *(uint4*)&sA[s][sbase]     = p0;
        *(uint4*)&sA[s][sbase + 4] = p1;
        p0.x = __float_as_uint(bv0.x); p0.y = __float_as_uint(bv1.x);
        p0.z = __float_as_uint(bv0.y); p0.w = __float_as_uint(bv1.y);
        p1.x = __float_as_uint(bv0.z); p1.y = __float_as_uint(bv1.z);
        p1.z = __float_as_uint(bv0.w); p1.w = __float_as_uint(bv1.w);
        *(uint4*)&sB[s][sbase]     = p0;
        *(uint4*)&sB[s][sbase + 4] = p1;
    };

    fetch(0);
    store_stage(0);
    __syncthreads();

    const int steps = K >> 4;
    for (int it = 0; it < steps; it++) {
        const int s = it & 1;
        if (it + 1 < steps) fetch((it + 1) << 4);

#pragma unroll
        for (int k8 = 0; k8 < 2; k8++) {
            const unsigned* baseA = &sA[s][k8 * 1024 + qc * 2];
            const unsigned* baseB = &sB[s][k8 * 1024 + qc * 2];
            uint2 afl[4], afh[4], bf[4];
#pragma unroll
            for (int mt = 0; mt < 4; mt++) {
                const int r = wm + mt * 16 + qr;
                afl[mt] = *(const uint2*)&baseA[r * 8];
                afh[mt] = *(const uint2*)&baseA[(r + 8) * 8];
            }
#pragma unroll
            for (int nt = 0; nt < 4; nt++) {
                const int n = wn + nt * 8 + qr;
                bf[nt] = *(const uint2*)&baseB[n * 8];
            }
#pragma unroll
            for (int mt = 0; mt < 4; mt++)
#pragma unroll
                for (int nt = 0; nt < 4; nt++)
                    mma_tf32(acc[mt][nt],
                             afl[mt].x, afh[mt].x, afl[mt].y, afh[mt].y,
                             bf[nt].x, bf[nt].y);
        }

        if (it + 1 < steps) store_stage(s ^ 1);
        __syncthreads();
    }

#pragma unroll
    for (int mt = 0; mt < 4; mt++) {
#pragma unroll
        for (int nt = 0; nt < 4; nt++) {
#pragma unroll
            for (int half = 0; half < 2; half++) {
                const int m = m0 + wm + mt * 16 + qr + half * 8;
                if (m >= Mvalid) continue;
                const int col = n0 + wn + nt * 8 + 2 * qc;
#pragma unroll
                for (int q = 0; q < 2; q++) {
                    const int n = col + q;
                    if (n >= N) continue;
                    float v = acc[mt][nt][half * 2 + q];
                    if (bias)  v += bias[n];
                    if (bias2) v += bias2[n];
                    if (storemode == 0) {
                        C[(size_t)m * N + n] = v;
                    } else {
                        const int t = m >> 6, b = m & 63;
                        C[((size_t)b * Ll + t + 1) * Vv + n] = v;
                    }
                }
            }
        }
    }
}

// ============ tensor-core gates GEMM (R10: truncation) =======================
// grid (16, 8): n0 = bx*128, K chunk s = by (128 wide). Partials P[s][64][2048].
__global__ __launch_bounds__(256)
void gates_tc(const float* __restrict__ W_ih,
              const float* __restrict__ W_hh)
{
    __shared__ unsigned sA[2][1024];
    __shared__ unsigned sB[2][2048];

    const int tid  = threadIdx.x;
    const int n0   = blockIdx.x * 128;
    const int s    = blockIdx.y;
    const int kbeg = s * 128;
    const int lane = tid & 31;
    const int wid  = tid >> 5;
    const int wm   = (wid & 1) * 32;
    const int wn   = (wid >> 1) * 32;
    const int qr   = lane >> 2;
    const int qc   = lane & 3;

    const int lrow = tid >> 1;
    const int lk   = (tid & 1) << 3;
    const int k8i  = lk >> 3;
    const int sbB  = k8i * 1024 + lrow * 8;
    const int sbA  = k8i * 512  + lrow * 8;

    const float* abase = (s < 4) ? g_context : g_h;
    const int    akoff = (s < 4) ? kbeg : (kbeg - 512);
    const float* asrc  = abase + (size_t)lrow * 512 + akoff;

    const int brn = n0 + lrow;
    const float* bsrc = (s < 4) ? (W_ih + (size_t)brn * 1024 + 512 + kbeg)
                                : (W_hh + (size_t)brn * 512 + (kbeg - 512));

    float acc[2][4][4];
#pragma unroll
    for (int i = 0; i < 2; i++)
#pragma unroll
        for (int j = 0; j < 4; j++)
#pragma unroll
            for (int q = 0; q < 4; q++) acc[i][j][q] = 0.0f;

    float4 av0, av1, bv0, bv1;
    auto fetch = [&](int k0) {
        if (tid < 128) {
            av0 = *(const float4*)(asrc + k0 + lk);
            av1 = *(const float4*)(asrc + k0 + lk + 4);
        }
        bv0 = *(const float4*)(bsrc + k0 + lk);
        bv1 = *(const float4*)(bsrc + k0 + lk + 4);
    };
    auto store_stage = [&](int st) {
        uint4 p0, p1;
        if (tid < 128) {
            p0.x = __float_as_uint(av0.x); p0.y = __float_as_uint(av1.x);
            p0.z = __float_as_uint(av0.y); p0.w = __float_as_uint(av1.y);
            p1.x = __float_as_uint(av0.z); p1.y = __float_as_uint(av1.z);
            p1.z = __float_as_uint(av0.w); p1.w = __float_as_uint(av1.w);
            *(uint4*)&sA[st][sbA]     = p0;
            *(uint4*)&sA[st][sbA + 4] = p1;
        }
        p0.x = __float_as_uint(bv0.x); p0.y = __float_as_uint(bv1.x);
        p0.z = __float_as_uint(bv0.y); p0.w = __float_as_uint(bv1.y);
        p1.x = __float_as_uint(bv0.z); p1.y = __float_as_uint(bv1.z);
        p1.z = __float_as_uint(bv0.w); p1.w = __float_as_uint(bv1.w);
        *(uint4*)&sB[st][sbB]     = p0;
        *(uint4*)&sB[st][sbB + 4] = p1;
    };

    fetch(0);
    store_stage(0);
    __syncthreads();

    for (int it = 0; it < 8; it++) {
        const int st = it & 1;
        if (it + 1 < 8) fetch((it + 1) << 4);

#pragma unroll
        for (int k8 = 0; k8 < 2; k8++) {
            const unsigned* baseA = &sA[st][k8 * 512 + qc * 2];
            const unsigned* baseB = &sB[st][k8 * 1024 + qc * 2];
            uint2 afl[2], afh[2], bf[4];
#pragma unroll
            for (int mt = 0; mt < 2; mt++) {
                const int r = wm + mt * 16 + qr;
                afl[mt] = *(const uint2*)&baseA[r * 8];
                afh[mt] = *(const uint2*)&baseA[(r + 8) * 8];
            }
#pragma unroll
            for (int nt = 0; nt < 4; nt++) {
                const int n = wn + nt * 8 + qr;
                bf[nt] = *(const uint2*)&baseB[n * 8];
            }
#pragma unroll
            for (int mt = 0; mt < 2; mt++)
#pragma unroll
                for (int nt = 0; nt < 4; nt++)
                    mma_tf32(acc[mt][nt],
                             afl[mt].x, afh[mt].x, afl[mt].y, afh[mt].y,
                             bf[nt].x, bf[nt].y);
        }

        if (it + 1 < 8) store_stage(st ^ 1);
        __syncthreads();
    }

    float* P = g_gates_part + (size_t)s * 64 * 2048;
#pragma unroll
    for (int mt = 0; mt < 2; mt++) {
#pragma unroll
        for (int nt = 0; nt < 4; nt++) {
#pragma unroll
            for (int half = 0; half < 2; half++) {
                const int m = wm + mt * 16 + qr + half * 8;
                const int n = n0 + wn + nt * 8 + 2 * qc;
                float2 v2 = make_float2(acc[mt][nt][half * 2], acc[mt][nt][half * 2 + 1]);
                *(float2*)&P[(size_t)m * 2048 + n] = v2;
            }
        }
    }
}

// ============ dec GEMM: ALL global loads hoisted (MLP=16, one exposure) ======
// grid (8, 4): n0 = bx*64, K chunk s = by (128 wide). P[s][64][512].
__global__ __launch_bounds__(256)
void gemm64_split(const float* __restrict__ A1,
                  const float* __restrict__ W1,
                  float* __restrict__ P)
{
    __shared__ float As[16][64];
    __shared__ float Ws[16][64];
    const int tid = threadIdx.x;
    const int n0 = blockIdx.x * 64;
    const int s  = blockIdx.y;
    const int kbeg = s * 128;

    const int row = tid >> 2;
    const int kc  = (tid & 3) << 2;
    const int tx = tid & 15, ty = tid >> 4;

    // hoist all 8+8 float4 loads up front — single latency exposure
    float4 avs[8], wvs[8];
#pragma unroll
    for (int i = 0; i < 8; i++) {
        const int k0 = kbeg + i * 16;
        avs[i] = *(const float4*)(A1 + (size_t)row * 512 + k0 + kc);
        wvs[i] = *(const float4*)(W1 + (size_t)(n0 + row) * 512 + k0 + kc);
    }

    float acc[4][4];
#pragma unroll
    for (int i = 0; i < 4; i++)
#pragma unroll
        for (int j = 0; j < 4; j++) acc[i][j] = 0.0f;

#pragma unroll
    for (int i = 0; i < 8; i++) {
        float4 av = avs[i], wv = wvs[i];
        As[kc+0][row] = av.x; As[kc+1][row] = av.y; As[kc+2][row] = av.z; As[kc+3][row] = av.w;
        Ws[kc+0][row] = wv.x; Ws[kc+1][row] = wv.y; Ws[kc+2][row] = wv.z; Ws[kc+3][row] = wv.w;
        __syncthreads();
#pragma unroll
        for (int kk = 0; kk < 16; kk++) {
            float4 a4 = *(const float4*)&As[kk][ty << 2];
            float4 w4 = *(const float4*)&Ws[kk][tx << 2];
            float a_[4] = {a4.x, a4.y, a4.z, a4.w};
            float w_[4] = {w4.x, w4.y, w4.z, w4.w};
#pragma unroll
            for (int ii = 0; ii < 4; ii++)
#pragma unroll
                for (int jj = 0; jj < 4; jj++) acc[ii][jj] += a_[ii] * w_[jj];
        }
        __syncthreads();
    }

#pragma unroll
    for (int i = 0; i < 4; i++) {
        const int m = (ty << 2) + i;
        float4 o = make_float4(acc[i][0], acc[i][1], acc[i][2], acc[i][3]);
        *(float4*)(P + ((size_t)(s * 64 + m) * 512 + n0 + (tx << 2))) = o;
    }
}

// ============ fused attention ===============================================
__global__ void attn_step(const float* __restrict__ enc_out,
                          const float* __restrict__ dec_bv,
                          const float* __restrict__ eW,
                          const float* __restrict__ eb)
{
    __shared__ float dec_s[Aa];
    __shared__ float eW_s[Aa];
    __shared__ float sc[224];
    __shared__ float red[512];

    const int b = blockIdx.x, tid = threadIdx.x;

    {
        float v = dec_bv[tid];
#pragma unroll
        for (int s = 0; s < 4; s++) v += g_dec_part[(size_t)(s * 64 + b) * Aa + tid];
        dec_s[tid] = v;
        eW_s[tid] = eW[tid];
    }
    const float eb0 = eb[0];
    __syncthreads();

    const int wid = tid >> 5, lane = tid & 31;
    for (int n = wid; n < Nn; n += 16) {
        const float* ep = g_enc_proj + ((size_t)b * Nn + n) * Aa;
        float acc = 0.0f;
#pragma unroll 4
        for (int a = lane; a < Aa; a += 32)
            acc += tanh_fast(ep[a] + dec_s[a]) * eW_s[a];
#pragma unroll
        for (int o = 16; o; o >>= 1) acc += __shfl_xor_sync(0xffffffffu, acc, o);
        if (lane == 0) sc[n] = acc + eb0;
    }
    __syncthreads();

    float v = (tid < Nn) ? sc[tid] : -1e30f;
    red[tid] = v; __syncthreads();
    for (int s = 256; s; s >>= 1) { if (tid < s) red[tid] = fmaxf(red[tid], red[tid+s]); __syncthreads(); }
    const float mx = red[0]; __syncthreads();
    float e = (tid < Nn) ? __expf(v - mx) : 0.0f;
    red[tid] = e; __syncthreads();
    for (int s = 256; s; s >>= 1) { if (tid < s) red[tid] += red[tid+s]; __syncthreads(); }
    const float inv = 1.0f / red[0];
    if (tid < Nn) sc[tid] = e * inv;
    __syncthreads();

    const float* eo = enc_out + (size_t)b * Nn * Hh + tid;
    float acc = 0.0f;
#pragma unroll 4
    for (int n = 0; n < Nn; n++) acc += sc[n] * eo[(size_t)n * Hh];
    g_context[b * Hh + tid] = acc;
}

// ============ LSTM cell: fold 8 gate partials + nonlinearity =================
__global__ void cell_update(int t)
{
    const int b = blockIdx.x, u = threadIdx.x;
    const float* gx = g_gates_x + ((size_t)t * Bb + b) * 4 * Hh;
    float g[4];
#pragma unroll
    for (int gi = 0; gi < 4; gi++) {
        const int col = gi * Hh + u;
        float v = gx[col];
#pragma unroll
        for (int s = 0; s < 8; s++) v += g_gates_part[(size_t)(s * 64 + b) * (4*Hh) + col];
        g[gi] = v;
    }
    const int idx = b * Hh + u;
    const float cn = sigmoid_fast(g[1]) * g_c[idx] + sigmoid_fast(g[0]) * tanh_fast(g[2]);
    const float hn = sigmoid_fast(g[3]) * tanh_fast(cn);
    g_c[idx] = cn;
    g_h[idx] = hn;
    g_hall[(size_t)(t * Bb + b) * Hh + u] = hn;
}

// ============ init + zero (fused) ============================================
__global__ void init_all(float* __restrict__ out)
{
    const int gi = blockIdx.x * blockDim.x + threadIdx.x;
    if (gi < Bb * Hh) { g_h[gi] = 0.0f; g_c[gi] = 0.0f; }
    for (int i = gi; i < Bb * Vv; i += gridDim.x * blockDim.x) {
        const int b = i / Vv, v = i - b * Vv;
        out[(size_t)b * Ll * Vv + v] = 0.0f;
    }
}

// ============ launch =========================================================
extern "C" void kernel_launch(void* const* d_in, const int* in_sizes, int n_in,
                              void* d_out, int out_size)
{
    const float* enc_out  = (const float*)d_in[0];
    const int*   captions = (const int*)d_in[1];
    const float* emb      = (const float*)d_in[2];
    const float* W_ih     = (const float*)d_in[3];
    const float* W_hh     = (const float*)d_in[4];
    const float* b_ih     = (const float*)d_in[5];
    const float* b_hh     = (const float*)d_in[6];
    const float* enc_W    = (const float*)d_in[7];
    const float* enc_b    = (const float*)d_in[8];
    const float* dec_W    = (const float*)d_in[9];
    const float* dec_b    = (const float*)d_in[10];
    const float* energy_W = (const float*)d_in[11];
    const float* energy_b = (const float*)d_in[12];
    const float* fc_W     = (const float*)d_in[13];
    const float* fc_b     = (const float*)d_in[14];
    float* out = (float*)d_out;

    float *p_enc_proj, *p_gates_x, *p_hall, *p_h, *p_dec_part;
    cudaGetSymbolAddress((void**)&p_enc_proj, g_enc_proj);
    cudaGetSymbolAddress((void**)&p_gates_x,  g_gates_x);
    cudaGetSymbolAddress((void**)&p_hall,     g_hall);
    cudaGetSymbolAddress((void**)&p_h,        g_h);
    cudaGetSymbolAddress((void**)&p_dec_part, g_dec_part);

    init_all<<<256, 256>>>(out);

    // enc_proj : [12544, 512] K=512
    gemm_tc<<<dim3(512/128, 12544/128), 256>>>(enc_out, enc_W, 512, enc_b, nullptr,
                                               p_enc_proj, 12544, 512, 512, nullptr, 0);
    // gates_x : [1216, 2048] K=512 (embedding gather)
    gemm_tc<<<dim3(2048/128, 10), 256>>>(emb, W_ih, 1024, b_ih, b_hh,
                                         p_gates_x, 1216, 2048, 512, captions, 0);

    for (int t = 0; t < Tt; t++) {
        // dec partials (fp32 SIMT, split-K=4, all-loads-hoisted)
        gemm64_split<<<dim3(Aa/64, 4), 256>>>(p_h, dec_W, p_dec_part);
        // dec-fold + scores + softmax + context
        attn_step<<<Bb, 512>>>(enc_out, dec_b, energy_W, energy_b);
        // gates partials via tensor cores, split-K=8
        gates_tc<<<dim3(16, 8), 256>>>(W_ih, W_hh);
        // cell (folds 8 partials)
        cell_update<<<Bb, Hh>>>(t);
    }

    // fc : [1216, 20000] K=512
    gemm_tc<<<dim3((Vv + 127)/128, 10), 256>>>(p_hall, fc_W, 512, fc_b, nullptr,
                                               out, 1216, Vv, 512, nullptr, 1);
}

// round 17
// speedup vs baseline: 1.2519x; 1.1694x over previous
#include <cuda_runtime.h>
#include <cstdint>

#define Bb 64
#define Nn 196
#define Hh 512
#define Aa 512
#define Vv 20000
#define Ll 20
#define Tt 19

// ---------------- scratch ----------------------------------------------------
__device__ float g_enc_proj[Bb*Nn*Aa];        // 25.7 MB
__device__ float g_h[Bb*Hh];
__device__ float g_c[Bb*Hh];
__device__ float g_context[Bb*Hh];
__device__ float g_gates_x[Tt*Bb*4*Hh];
__device__ float g_dec_part[8*Bb*Aa];         // split-K=8 dec partials
__device__ float g_gates_part[8*Bb*4*Hh];     // split-K=8 gate partials (4 MB)
__device__ float g_hall[1280*Hh];

__device__ __forceinline__ float tanh_fast(float x) {
    float y; asm("tanh.approx.f32 %0, %1;" : "=f"(y) : "f"(x)); return y;
}
__device__ __forceinline__ float sigmoid_fast(float x) {
    return 1.0f / (1.0f + __expf(-x));
}
// HMMA tf32 ignores the low 13 mantissa bits of the 32-bit operand register,
// so raw fp32 acts as truncation-rounded tf32 (R10 numerics; rel_err 5.6e-4).
__device__ __forceinline__ void mma_tf32(float c[4],
                                         unsigned a0, unsigned a1, unsigned a2, unsigned a3,
                                         unsigned b0, unsigned b1) {
    asm("mma.sync.aligned.m16n8k8.row.col.f32.tf32.tf32.f32 "
        "{%0,%1,%2,%3}, {%4,%5,%6,%7}, {%8,%9}, {%0,%1,%2,%3};"
        : "+f"(c[0]), "+f"(c[1]), "+f"(c[2]), "+f"(c[3])
        : "r"(a0), "r"(a1), "r"(a2), "r"(a3), "r"(b0), "r"(b1));
}

// ============ tensor-core tf32 NT GEMM (proven R10: 128x128, 64x32 warps) ====
__global__ __launch_bounds__(256, 2)
void gemm_tc(const float* __restrict__ A,
             const float* __restrict__ Bw, int ldb,
             const float* __restrict__ bias,
             const float* __restrict__ bias2,
             float* __restrict__ C,
             int Mvalid, int N, int K,
             const int* __restrict__ caps, int storemode)
{
    __shared__ unsigned sA[2][2048];
    __shared__ unsigned sB[2][2048];

    const int tid  = threadIdx.x;
    const int m0   = blockIdx.y * 128;
    const int n0   = blockIdx.x * 128;
    const int lane = tid & 31;
    const int wid  = tid >> 5;
    const int wm   = (wid & 1) * 64;
    const int wn   = (wid >> 1) * 32;
    const int qr   = lane >> 2;
    const int qc   = lane & 3;

    const int lrow = tid >> 1;
    const int lk   = (tid & 1) << 3;
    const int sbase = (lk >> 3) * 1024 + lrow * 8;

    const float* arow;
    {
        int am = m0 + lrow;
        if (caps) {
            int mm = (am < Mvalid) ? am : 0;
            int ci = caps[(mm & 63) * Ll + (mm >> 6)];
            ci = ci < 0 ? 0 : (ci >= Vv ? Vv - 1 : ci);
            arow = A + (size_t)ci * K;
        } else {
            int mm = (am < Mvalid) ? am : (Mvalid - 1);
            arow = A + (size_t)mm * K;
        }
    }
    const int bn = n0 + lrow;
    const bool bval = (bn < N);
    const float* brow = Bw + (size_t)(bval ? bn : 0) * ldb;

    float acc[4][4][4];
#pragma unroll
    for (int i = 0; i < 4; i++)
#pragma unroll
        for (int j = 0; j < 4; j++)
#pragma unroll
            for (int q = 0; q < 4; q++) acc[i][j][q] = 0.0f;

    float4 av0, av1, bv0, bv1;
    auto fetch = [&](int k0) {
        av0 = *(const float4*)(arow + k0 + lk);
        av1 = *(const float4*)(arow + k0 + lk + 4);
        bv0 = bval ? *(const float4*)(brow + k0 + lk)     : make_float4(0.f,0.f,0.f,0.f);
        bv1 = bval ? *(const float4*)(brow + k0 + lk + 4) : make_float4(0.f,0.f,0.f,0.f);
    };
    auto store_stage = [&](int s) {
        uint4 p0, p1;
        p0.x = __float_as_uint(av0.x); p0.y = __float_as_uint(av1.x);
        p0.z = __float_as_uint(av0.y); p0.w = __float_as_uint(av1.y);
        p1.x = __float_as_uint(av0.z); p1.y = __float_as_uint(av1.z);
        p1.z = __float_as_uint(av0.w); p1.w = __float_as_uint(av1.w);
        *(uint4*)&sA[s][sbase]     = p0;
        *(uint4*)&sA[s][sbase + 4] = p1;
        p0.x = __float_as_uint(bv0.x); p0.y = __float_as_uint(bv1.x);
        p0.z = __float_as_uint(bv0.y); p0.w = __float_as_uint(bv1.y);
        p1.x = __float_as_uint(bv0.z); p1.y = __float_as_uint(bv1.z);
        p1.z = __float_as_uint(bv0.w); p1.w = __float_as_uint(bv1.w);
        *(uint4*)&sB[s][sbase]     = p0;
        *(uint4*)&sB[s][sbase + 4] = p1;
    };

    fetch(0);
    store_stage(0);
    __syncthreads();

    const int steps = K >> 4;
    for (int it = 0; it < steps; it++) {
        const int s = it & 1;
        if (it + 1 < steps) fetch((it + 1) << 4);

#pragma unroll
        for (int k8 = 0; k8 < 2; k8++) {
            const unsigned* baseA = &sA[s][k8 * 1024 + qc * 2];
            const unsigned* baseB = &sB[s][k8 * 1024 + qc * 2];
            uint2 afl[4], afh[4], bf[4];
#pragma unroll
            for (int mt = 0; mt < 4; mt++) {
                const int r = wm + mt * 16 + qr;
                afl[mt] = *(const uint2*)&baseA[r * 8];
                afh[mt] = *(const uint2*)&baseA[(r + 8) * 8];
            }
#pragma unroll
            for (int nt = 0; nt < 4; nt++) {
                const int n = wn + nt * 8 + qr;
                bf[nt] = *(const uint2*)&baseB[n * 8];
            }
#pragma unroll
            for (int mt = 0; mt < 4; mt++)
#pragma unroll
                for (int nt = 0; nt < 4; nt++)
                    mma_tf32(acc[mt][nt],
                             afl[mt].x, afh[mt].x, afl[mt].y, afh[mt].y,
                             bf[nt].x, bf[nt].y);
        }

        if (it + 1 < steps) store_stage(s ^ 1);
        __syncthreads();
    }

#pragma unroll
    for (int mt = 0; mt < 4; mt++) {
#pragma unroll
        for (int nt = 0; nt < 4; nt++) {
#pragma unroll
            for (int half = 0; half < 2; half++) {
                const int m = m0 + wm + mt * 16 + qr + half * 8;
                if (m >= Mvalid) continue;
                const int col = n0 + wn + nt * 8 + 2 * qc;
#pragma unroll
                for (int q = 0; q < 2; q++) {
                    const int n = col + q;
                    if (n >= N) continue;
                    float v = acc[mt][nt][half * 2 + q];
                    if (bias)  v += bias[n];
                    if (bias2) v += bias2[n];
                    if (storemode == 0) {
                        C[(size_t)m * N + n] = v;
                    } else {
                        const int t = m >> 6, b = m & 63;
                        C[((size_t)b * Ll + t + 1) * Vv + n] = v;
                    }
                }
            }
        }
    }
}

// ============ tensor-core gates GEMM (R10: truncation) =======================
// grid (16, 8): n0 = bx*128, K chunk s = by (128 wide). Partials P[s][64][2048].
__global__ __launch_bounds__(256)
void gates_tc(const float* __restrict__ W_ih,
              const float* __restrict__ W_hh)
{
    __shared__ unsigned sA[2][1024];
    __shared__ unsigned sB[2][2048];

    const int tid  = threadIdx.x;
    const int n0   = blockIdx.x * 128;
    const int s    = blockIdx.y;
    const int kbeg = s * 128;
    const int lane = tid & 31;
    const int wid  = tid >> 5;
    const int wm   = (wid & 1) * 32;
    const int wn   = (wid >> 1) * 32;
    const int qr   = lane >> 2;
    const int qc   = lane & 3;

    const int lrow = tid >> 1;
    const int lk   = (tid & 1) << 3;
    const int k8i  = lk >> 3;
    const int sbB  = k8i * 1024 + lrow * 8;
    const int sbA  = k8i * 512  + lrow * 8;

    const float* abase = (s < 4) ? g_context : g_h;
    const int    akoff = (s < 4) ? kbeg : (kbeg - 512);
    const float* asrc  = abase + (size_t)lrow * 512 + akoff;

    const int brn = n0 + lrow;
    const float* bsrc = (s < 4) ? (W_ih + (size_t)brn * 1024 + 512 + kbeg)
                                : (W_hh + (size_t)brn * 512 + (kbeg - 512));

    float acc[2][4][4];
#pragma unroll
    for (int i = 0; i < 2; i++)
#pragma unroll
        for (int j = 0; j < 4; j++)
#pragma unroll
            for (int q = 0; q < 4; q++) acc[i][j][q] = 0.0f;

    float4 av0, av1, bv0, bv1;
    auto fetch = [&](int k0) {
        if (tid < 128) {
            av0 = *(const float4*)(asrc + k0 + lk);
            av1 = *(const float4*)(asrc + k0 + lk + 4);
        }
        bv0 = *(const float4*)(bsrc + k0 + lk);
        bv1 = *(const float4*)(bsrc + k0 + lk + 4);
    };
    auto store_stage = [&](int st) {
        uint4 p0, p1;
        if (tid < 128) {
            p0.x = __float_as_uint(av0.x); p0.y = __float_as_uint(av1.x);
            p0.z = __float_as_uint(av0.y); p0.w = __float_as_uint(av1.y);
            p1.x = __float_as_uint(av0.z); p1.y = __float_as_uint(av1.z);
            p1.z = __float_as_uint(av0.w); p1.w = __float_as_uint(av1.w);
            *(uint4*)&sA[st][sbA]     = p0;
            *(uint4*)&sA[st][sbA + 4] = p1;
        }
        p0.x = __float_as_uint(bv0.x); p0.y = __float_as_uint(bv1.x);
        p0.z = __float_as_uint(bv0.y); p0.w = __float_as_uint(bv1.y);
        p1.x = __float_as_uint(bv0.z); p1.y = __float_as_uint(bv1.z);
        p1.z = __float_as_uint(bv0.w); p1.w = __float_as_uint(bv1.w);
        *(uint4*)&sB[st][sbB]     = p0;
        *(uint4*)&sB[st][sbB + 4] = p1;
    };

    fetch(0);
    store_stage(0);
    __syncthreads();

    for (int it = 0; it < 8; it++) {
        const int st = it & 1;
        if (it + 1 < 8) fetch((it + 1) << 4);

#pragma unroll
        for (int k8 = 0; k8 < 2; k8++) {
            const unsigned* baseA = &sA[st][k8 * 512 + qc * 2];
            const unsigned* baseB = &sB[st][k8 * 1024 + qc * 2];
            uint2 afl[2], afh[2], bf[4];
#pragma unroll
            for (int mt = 0; mt < 2; mt++) {
                const int r = wm + mt * 16 + qr;
                afl[mt] = *(const uint2*)&baseA[r * 8];
                afh[mt] = *(const uint2*)&baseA[(r + 8) * 8];
            }
#pragma unroll
            for (int nt = 0; nt < 4; nt++) {
                const int n = wn + nt * 8 + qr;
                bf[nt] = *(const uint2*)&baseB[n * 8];
            }
#pragma unroll
            for (int mt = 0; mt < 2; mt++)
#pragma unroll
                for (int nt = 0; nt < 4; nt++)
                    mma_tf32(acc[mt][nt],
                             afl[mt].x, afh[mt].x, afl[mt].y, afh[mt].y,
                             bf[nt].x, bf[nt].y);
        }

        if (it + 1 < 8) store_stage(st ^ 1);
        __syncthreads();
    }

    float* P = g_gates_part + (size_t)s * 64 * 2048;
#pragma unroll
    for (int mt = 0; mt < 2; mt++) {
#pragma unroll
        for (int nt = 0; nt < 4; nt++) {
#pragma unroll
            for (int half = 0; half < 2; half++) {
                const int m = wm + mt * 16 + qr + half * 8;
                const int n = n0 + wn + nt * 8 + 2 * qc;
                float2 v2 = make_float2(acc[mt][nt][half * 2], acc[mt][nt][half * 2 + 1]);
                *(float2*)&P[(size_t)m * 2048 + n] = v2;
            }
        }
    }
}

// ============ dec GEMM: split-K=8 (KC=64), all loads hoisted =================
// grid (8, 8): n0 = bx*64, K chunk s = by (64 wide). P[s][64][512].
__global__ __launch_bounds__(256)
void gemm64_split(const float* __restrict__ A1,
                  const float* __restrict__ W1,
                  float* __restrict__ P)
{
    __shared__ float As[16][64];
    __shared__ float Ws[16][64];
    const int tid = threadIdx.x;
    const int n0 = blockIdx.x * 64;
    const int s  = blockIdx.y;
    const int kbeg = s * 64;

    const int row = tid >> 2;
    const int kc  = (tid & 3) << 2;
    const int tx = tid & 15, ty = tid >> 4;

    // hoist all 4+4 float4 loads up front — single latency exposure
    float4 avs[4], wvs[4];
#pragma unroll
    for (int i = 0; i < 4; i++) {
        const int k0 = kbeg + i * 16;
        avs[i] = *(const float4*)(A1 + (size_t)row * 512 + k0 + kc);
        wvs[i] = *(const float4*)(W1 + (size_t)(n0 + row) * 512 + k0 + kc);
    }

    float acc[4][4];
#pragma unroll
    for (int i = 0; i < 4; i++)
#pragma unroll
        for (int j = 0; j < 4; j++) acc[i][j] = 0.0f;

#pragma unroll
    for (int i = 0; i < 4; i++) {
        float4 av = avs[i], wv = wvs[i];
        As[kc+0][row] = av.x; As[kc+1][row] = av.y; As[kc+2][row] = av.z; As[kc+3][row] = av.w;
        Ws[kc+0][row] = wv.x; Ws[kc+1][row] = wv.y; Ws[kc+2][row] = wv.z; Ws[kc+3][row] = wv.w;
        __syncthreads();
#pragma unroll
        for (int kk = 0; kk < 16; kk++) {
            float4 a4 = *(const float4*)&As[kk][ty << 2];
            float4 w4 = *(const float4*)&Ws[kk][tx << 2];
            float a_[4] = {a4.x, a4.y, a4.z, a4.w};
            float w_[4] = {w4.x, w4.y, w4.z, w4.w};
#pragma unroll
            for (int ii = 0; ii < 4; ii++)
#pragma unroll
                for (int jj = 0; jj < 4; jj++) acc[ii][jj] += a_[ii] * w_[jj];
        }
        __syncthreads();
    }

#pragma unroll
    for (int i = 0; i < 4; i++) {
        const int m = (ty << 2) + i;
        float4 o = make_float4(acc[i][0], acc[i][1], acc[i][2], acc[i][3]);
        *(float4*)(P + ((size_t)(s * 64 + m) * 512 + n0 + (tx << 2))) = o;
    }
}

// ============ fused attention ===============================================
__global__ void attn_step(const float* __restrict__ enc_out,
                          const float* __restrict__ dec_bv,
                          const float* __restrict__ eW,
                          const float* __restrict__ eb)
{
    __shared__ float dec_s[Aa];
    __shared__ float eW_s[Aa];
    __shared__ float sc[224];
    __shared__ float red[512];

    const int b = blockIdx.x, tid = threadIdx.x;

    {
        float v = dec_bv[tid];
#pragma unroll
        for (int s = 0; s < 8; s++) v += g_dec_part[(size_t)(s * 64 + b) * Aa + tid];
        dec_s[tid] = v;
        eW_s[tid] = eW[tid];
    }
    const float eb0 = eb[0];
    __syncthreads();

    const int wid = tid >> 5, lane = tid & 31;
    for (int n = wid; n < Nn; n += 16) {
        const float* ep = g_enc_proj + ((size_t)b * Nn + n) * Aa;
        float acc = 0.0f;
#pragma unroll 4
        for (int a = lane; a < Aa; a += 32)
            acc += tanh_fast(ep[a] + dec_s[a]) * eW_s[a];
#pragma unroll
        for (int o = 16; o; o >>= 1) acc += __shfl_xor_sync(0xffffffffu, acc, o);
        if (lane == 0) sc[n] = acc + eb0;
    }
    __syncthreads();

    float v = (tid < Nn) ? sc[tid] : -1e30f;
    red[tid] = v; __syncthreads();
    for (int s = 256; s; s >>= 1) { if (tid < s) red[tid] = fmaxf(red[tid], red[tid+s]); __syncthreads(); }
    const float mx = red[0]; __syncthreads();
    float e = (tid < Nn) ? __expf(v - mx) : 0.0f;
    red[tid] = e; __syncthreads();
    for (int s = 256; s; s >>= 1) { if (tid < s) red[tid] += red[tid+s]; __syncthreads(); }
    const float inv = 1.0f / red[0];
    if (tid < Nn) sc[tid] = e * inv;
    __syncthreads();

    // context: 4 independent accumulator chains -> 4x MLP
    const float* eo = enc_out + (size_t)b * Nn * Hh + tid;
    float a0 = 0.f, a1 = 0.f, a2 = 0.f, a3 = 0.f;
#pragma unroll 4
    for (int n = 0; n < 196; n += 4) {
        a0 += sc[n]     * eo[(size_t)(n)     * Hh];
        a1 += sc[n + 1] * eo[(size_t)(n + 1) * Hh];
        a2 += sc[n + 2] * eo[(size_t)(n + 2) * Hh];
        a3 += sc[n + 3] * eo[(size_t)(n + 3) * Hh];
    }
    g_context[b * Hh + tid] = (a0 + a1) + (a2 + a3);
}

// ============ LSTM cell: fold 8 gate partials + nonlinearity =================
__global__ void cell_update(int t)
{
    const int b = blockIdx.x, u = threadIdx.x;
    const float* gx = g_gates_x + ((size_t)t * Bb + b) * 4 * Hh;
    float g[4];
#pragma unroll
    for (int gi = 0; gi < 4; gi++) {
        const int col = gi * Hh + u;
        float v = gx[col];
#pragma unroll
        for (int s = 0; s < 8; s++) v += g_gates_part[(size_t)(s * 64 + b) * (4*Hh) + col];
        g[gi] = v;
    }
    const int idx = b * Hh + u;
    const float cn = sigmoid_fast(g[1]) * g_c[idx] + sigmoid_fast(g[0]) * tanh_fast(g[2]);
    const float hn = sigmoid_fast(g[3]) * tanh_fast(cn);
    g_c[idx] = cn;
    g_h[idx] = hn;
    g_hall[(size_t)(t * Bb + b) * Hh + u] = hn;
}

// ============ init + zero (fused) ============================================
__global__ void init_all(float* __restrict__ out)
{
    const int gi = blockIdx.x * blockDim.x + threadIdx.x;
    if (gi < Bb * Hh) { g_h[gi] = 0.0f; g_c[gi] = 0.0f; }
    for (int i = gi; i < Bb * Vv; i += gridDim.x * blockDim.x) {
        const int b = i / Vv, v = i - b * Vv;
        out[(size_t)b * Ll * Vv + v] = 0.0f;
    }
}

// ============ launch =========================================================
extern "C" void kernel_launch(void* const* d_in, const int* in_sizes, int n_in,
                              void* d_out, int out_size)
{
    const float* enc_out  = (const float*)d_in[0];
    const int*   captions = (const int*)d_in[1];
    const float* emb      = (const float*)d_in[2];
    const float* W_ih     = (const float*)d_in[3];
    const float* W_hh     = (const float*)d_in[4];
    const float* b_ih     = (const float*)d_in[5];
    const float* b_hh     = (const float*)d_in[6];
    const float* enc_W    = (const float*)d_in[7];
    const float* enc_b    = (const float*)d_in[8];
    const float* dec_W    = (const float*)d_in[9];
    const float* dec_b    = (const float*)d_in[10];
    const float* energy_W = (const float*)d_in[11];
    const float* energy_b = (const float*)d_in[12];
    const float* fc_W     = (const float*)d_in[13];
    const float* fc_b     = (const float*)d_in[14];
    float* out = (float*)d_out;

    float *p_enc_proj, *p_gates_x, *p_hall, *p_h, *p_dec_part;
    cudaGetSymbolAddress((void**)&p_enc_proj, g_enc_proj);
    cudaGetSymbolAddress((void**)&p_gates_x,  g_gates_x);
    cudaGetSymbolAddress((void**)&p_hall,     g_hall);
    cudaGetSymbolAddress((void**)&p_h,        g_h);
    cudaGetSymbolAddress((void**)&p_dec_part, g_dec_part);

    init_all<<<256, 256>>>(out);

    // enc_proj : [12544, 512] K=512
    gemm_tc<<<dim3(512/128, 12544/128), 256>>>(enc_out, enc_W, 512, enc_b, nullptr,
                                               p_enc_proj, 12544, 512, 512, nullptr, 0);
    // gates_x : [1216, 2048] K=512 (embedding gather)
    gemm_tc<<<dim3(2048/128, 10), 256>>>(emb, W_ih, 1024, b_ih, b_hh,
                                         p_gates_x, 1216, 2048, 512, captions, 0);

    for (int t = 0; t < Tt; t++) {
        // dec partials (fp32 SIMT, split-K=8, all-loads-hoisted)
        gemm64_split<<<dim3(Aa/64, 8), 256>>>(p_h, dec_W, p_dec_part);
        // dec-fold + scores + softmax + context
        attn_step<<<Bb, 512>>>(enc_out, dec_b, energy_W, energy_b);
        // gates partials via tensor cores, split-K=8
        gates_tc<<<dim3(16, 8), 256>>>(W_ih, W_hh);
        // cell (folds 8 partials)
        cell_update<<<Bb, Hh>>>(t);
    }

    // fc : [1216, 20000] K=512
    gemm_tc<<<dim3((Vv + 127)/128, 10), 256>>>(p_hall, fc_W, 512, fc_b, nullptr,
                                               out, 1216, Vv, 512, nullptr, 1);
}